// round 17
// baseline (speedup 1.0000x reference)
#include <cuda_runtime.h>
#include <cstdint>

#define BATCHN 4096
#define NI 784
#define NIP 800
#define WID 16000
#define WIDP 16384
#define NHID 4
#define NLAYERS 5
#define NCLS 10
#define NSLICE (BATCHN / 32)
#define GROUP (WID / NCLS)
#define HGRP (GROUP / 2)
#define KWORDS (HGRP / 32)

// Descriptor: (ia | na<<14) | (ib | nb<<14) << 15.
// Index bit 14 selects the complement copy (buf[16384+i] = ~buf[i]).
__device__ uint32_t g_gidx[NLAYERS][WIDP];

static __device__ __forceinline__ uint32_t read_bool(const void* __restrict__ p,
                                                     size_t e, int mode) {
    if (mode == 1) return ((const uint32_t*)p)[e] != 0u;
    if (mode == 0) return ((const uint8_t*)p)[e] != 0u;
    return ((const uint16_t*)p)[e] != 0u;
}

static __device__ __forceinline__ int mode_from_words(const uint32_t* w64v) {
    bool w32 = true, bf16 = true, u8 = true;
    for (int i = 0; i < 64; i++) {
        uint32_t w = w64v[i];
        if (!(w == 0u || w == 1u || w == 0x3F800000u)) w32 = false;
        uint32_t h0 = w & 0xFFFFu, h1 = w >> 16;
        if (!((h0 == 0u || h0 == 0x3F80u) && (h1 == 0u || h1 == 0x3F80u))) bf16 = false;
        if ((w & 0xFEFEFEFEu) != 0u) u8 = false;
    }
    return w32 ? 1 : (bf16 ? 2 : (u8 ? 0 : 1));
}

// ---------------------------------------------------------------------------
// prep_idx_k: descriptors with negation folded into the index (bit 14).
// PDL: triggers completion early so fused_k can run its pack phase under us.
// ---------------------------------------------------------------------------
__global__ void prep_idx_k(const void* __restrict__ x,
                           const int* __restrict__ ia0, const int* __restrict__ ib0,
                           const void* __restrict__ ng0,
                           const int* __restrict__ iah, const int* __restrict__ ibh,
                           const void* __restrict__ ngh) {
#if __CUDA_ARCH__ >= 900
    if (threadIdx.x == 0) cudaTriggerProgrammaticLaunchCompletion();
#endif
    __shared__ int s_mode;
    if (threadIdx.x == 0) {
        uint32_t w[64];
        const uint32_t* xw = (const uint32_t*)x;
#pragma unroll
        for (int i = 0; i < 64; i++) w[i] = xw[i];
        s_mode = mode_from_words(w);
    }
    __syncthreads();
    int mode = s_mode;

    int t = blockIdx.x * blockDim.x + threadIdx.x;
    if (t >= NLAYERS * WIDP) return;
    int layer = t / WIDP;
    int n = t - layer * WIDP;
    uint32_t d = 0;                       // pads read buf[0] & buf[0]: harmless
    if (n < WID) {
        uint32_t ia, ib, na, nb;
        if (layer == 0) {
            ia = (uint32_t)ia0[n];
            ib = (uint32_t)ib0[n];
            na = read_bool(ng0, 2 * (size_t)n, mode);
            nb = read_bool(ng0, 2 * (size_t)n + 1, mode);
        } else {
            int k = layer - 1;
            ia = (uint32_t)iah[(size_t)k * WID + n];
            ib = (uint32_t)ibh[(size_t)k * WID + n];
            na = read_bool(ngh, ((size_t)k * WID + n) * 2, mode);
            nb = read_bool(ngh, ((size_t)k * WID + n) * 2 + 1, mode);
        }
        d = (ia | (na << 14)) | ((ib | (nb << 14)) << 15);
    }
    g_gidx[layer][n] = d;
}

// ---------------------------------------------------------------------------
// Gate: plain AND of complement-indexed operands (negation is in the index).
// ---------------------------------------------------------------------------
static __device__ __forceinline__ uint32_t gate(uint32_t d,
                                                const uint32_t* __restrict__ hs) {
    return hs[d & 0x7FFFu] & hs[(d >> 15) & 0x7FFFu];
}

static __device__ __forceinline__ uint4 gate4(uint4 d, const uint32_t* __restrict__ hs) {
    uint4 r;
    r.x = gate(d.x, hs);
    r.y = gate(d.y, hs);
    r.z = gate(d.z, hs);
    r.w = gate(d.w, hs);
    return r;
}

static __device__ __forceinline__ uint4 inv4(uint4 v) {
    return make_uint4(~v.x, ~v.y, ~v.z, ~v.w);
}

// ---------------------------------------------------------------------------
// fused_k: one 128KB in-place activation buffer (plain [0,16384) +
// complement [16384,32768)). Per layer: all reads -> regs -> barrier ->
// stores (plain + complement) -> barrier. Uniform loop over all 5 layers.
// ---------------------------------------------------------------------------
#define BUF_WORDS 32768
#define STG_WORDS (32 * NIP / 4)
#define SM_BYTES ((BUF_WORDS + STG_WORDS) * 4)

__global__ void __launch_bounds__(1024) fused_k(const void* __restrict__ x,
                                                float* __restrict__ out) {
    extern __shared__ uint32_t sm[];
    uint32_t* buf = sm;                         // 32768 words
    uint8_t*  stg = (uint8_t*)(sm + BUF_WORDS); // 32 x NIP bytes
    __shared__ int partial[NCLS][2][32];
    __shared__ int s_mode;

    int s = blockIdx.x;
    int t = threadIdx.x;
    int wid = t >> 5;
    int lane = t & 31;

    // --- mode detection (stages through buf; overwritten later) ---
    if (t < 64) buf[t] = ((const uint32_t*)x)[t];
    __syncthreads();
    if (t == 0) s_mode = mode_from_words(buf);
    __syncthreads();
    int mode = s_mode;

    // --- Phase A: coalesced row loads. warp = sample row, lanes stride. ---
    {
        size_t rowbase = (size_t)(32 * s + wid) * NI;
        uint8_t* rowdst = stg + wid * NIP;
        for (int i = lane; i < NI; i += 32)
            rowdst[i] = (uint8_t)read_bool(x, rowbase + i, mode);
    }
    __syncthreads();

    // --- Phase B: transpose -> plain + complement packed input words. ---
    if (t < NI) {
        uint32_t acc = 0;
#pragma unroll
        for (int j = 0; j < 32; j++)
            acc |= (uint32_t)stg[j * NIP + t] << j;
        buf[t] = acc;
        buf[16384 + t] = ~acc;
    }
    __syncthreads();

    // --- PDL join: g_gidx must be complete from here on. ---
#if __CUDA_ARCH__ >= 900
    cudaGridDependencySynchronize();
#endif

    const uint4* gl = (const uint4*)g_gidx[0];
    uint4 d0 = gl[t];
    uint4 d1 = gl[1024 + t];
    uint4 d2 = gl[2048 + t];
    uint4 d3 = gl[3072 + t];

    // --- 5 uniform in-place layers ---
    uint4* b4 = (uint4*)buf;
#pragma unroll
    for (int L = 0; L < NLAYERS; L++) {
        uint4 r0 = gate4(d0, buf);
        uint4 r1 = gate4(d1, buf);
        uint4 r2 = gate4(d2, buf);
        uint4 r3 = gate4(d3, buf);
        __syncthreads();                 // all reads of layer L complete

        b4[t]        = r0;
        b4[1024 + t] = r1;
        b4[2048 + t] = r2;
        b4[3072 + t] = r3;
        b4[4096 + t] = inv4(r0);         // complement copies
        b4[5120 + t] = inv4(r1);
        b4[6144 + t] = inv4(r2);
        b4[7168 + t] = inv4(r3);

        if (L + 1 < NLAYERS) {           // prefetch next layer's descriptors
            const uint4* gn = (const uint4*)g_gidx[L + 1];
            d0 = gn[t];
            d1 = gn[1024 + t];
            d2 = gn[2048 + t];
            d3 = gn[3072 + t];
        }
        __syncthreads();                 // all writes visible
    }

    // --- In-CTA GroupSum from plain region (20 warps, 25 words/lane) ---
    if (wid < 2 * NCLS) {
        int c = wid >> 1;
        int hf = wid & 1;
        const uint32_t* __restrict__ p = buf + c * GROUP + hf * HGRP + lane;
        uint32_t s0 = 0, s1 = 0, s2 = 0, s3 = 0, s4 = 0;
#pragma unroll
        for (int k = 0; k < KWORDS; k++) {
            uint32_t cc = p[k * 32];
            uint32_t tt;
            tt = s0 & cc; s0 ^= cc; cc = tt;
            tt = s1 & cc; s1 ^= cc; cc = tt;
            tt = s2 & cc; s2 ^= cc; cc = tt;
            tt = s3 & cc; s3 ^= cc; cc = tt;
            s4 ^= cc;
        }
#pragma unroll
        for (int b = 0; b < 32; b++) {
            int tot = __popc(__ballot_sync(0xFFFFFFFFu, (s0 >> b) & 1u))
                    + 2  * __popc(__ballot_sync(0xFFFFFFFFu, (s1 >> b) & 1u))
                    + 4  * __popc(__ballot_sync(0xFFFFFFFFu, (s2 >> b) & 1u))
                    + 8  * __popc(__ballot_sync(0xFFFFFFFFu, (s3 >> b) & 1u))
                    + 16 * __popc(__ballot_sync(0xFFFFFFFFu, (s4 >> b) & 1u));
            if (lane == b) partial[c][hf][b] = tot;
        }
    }
    __syncthreads();

    if (t < NCLS * 32) {
        int c = t >> 5;
        int b = t & 31;
        out[(size_t)(s * 32 + b) * NCLS + c] =
            (float)(partial[c][0][b] + partial[c][1][b]);
    }
}

// ---------------------------------------------------------------------------
// Bind inputs BY ELEMENT COUNT. Output: float32 [BATCH, NCLS]
// ---------------------------------------------------------------------------
extern "C" void kernel_launch(void* const* d_in, const int* in_sizes, int n_in,
                              void* d_out, int out_size) {
    const void* x = nullptr;
    const int *ia0 = nullptr, *ib0 = nullptr, *iah = nullptr, *ibh = nullptr;
    const void *ng0 = nullptr, *ngh = nullptr;

    for (int i = 0; i < n_in; i++) {
        int sz = in_sizes[i];
        if (sz == BATCHN * NI) {
            x = d_in[i];
        } else if (sz == WID) {
            if (!ia0) ia0 = (const int*)d_in[i]; else ib0 = (const int*)d_in[i];
        } else if (sz == WID * 2) {
            ng0 = d_in[i];
        } else if (sz == NHID * WID) {
            if (!iah) iah = (const int*)d_in[i]; else ibh = (const int*)d_in[i];
        } else if (sz == NHID * WID * 2) {
            ngh = d_in[i];
        }
    }
    float* out = (float*)d_out;

    static bool attr_set = false;
    if (!attr_set) {
        cudaFuncSetAttribute(fused_k, cudaFuncAttributeMaxDynamicSharedMemorySize,
                             SM_BYTES);
        attr_set = true;
    }

    prep_idx_k<<<(NLAYERS * WIDP + 255) / 256, 256>>>(x, ia0, ib0, ng0, iah, ibh, ngh);

    // fused_k with Programmatic Dependent Launch.
    cudaLaunchConfig_t cfg = {};
    cfg.gridDim = dim3(NSLICE, 1, 1);
    cfg.blockDim = dim3(1024, 1, 1);
    cfg.dynamicSmemBytes = SM_BYTES;
    cfg.stream = 0;
    cudaLaunchAttribute attrs[1];
    attrs[0].id = cudaLaunchAttributeProgrammaticStreamSerialization;
    attrs[0].val.programmaticStreamSerializationAllowed = 1;
    cfg.attrs = attrs;
    cfg.numAttrs = 1;
    cudaLaunchKernelEx(&cfg, fused_k, x, out);
}